// round 3
// baseline (speedup 1.0000x reference)
#include <cuda_runtime.h>
#include <math.h>

// Problem dims (fixed)
#define BB 4
#define SS 1024
#define DM 512
#define HH 8
#define HDD 64
#define HIDD 2048
#define NT (BB*SS)                 // 4096 token rows
#define NDE ((size_t)NT*DM)        // 2097152
#define NHE ((size_t)NT*HIDD)      // 8388608
#define DDE ((size_t)DM*DM)        // 262144
#define GDE ((size_t)HIDD*DM)      // 1048576

// -------- scratch: one big __device__ array (no allocations allowed) --------
// layout (floats):
//  8*DDE  qkvo weights (wr/wi interleaved per linear)
//  6*GDE  gate/up/down weights
// 10*NDE  hr,hi,qr,qi,kr,ki,vr,vi,ar,ai
//  4*NHE  gr,gi,ur,ui
//  32M    scores (B*H*S*S)
__device__ float g_scratch[96468992];

// ---------------------------------------------------------------------------
__global__ __launch_bounds__(256) void make_w_kernel(const float* __restrict__ lm,
                                                     const float* __restrict__ ph,
                                                     float* __restrict__ wr,
                                                     float* __restrict__ wi, int n) {
    int i = blockIdx.x * 256 + threadIdx.x;
    if (i >= n) return;
    float m = expf(lm[i]);
    float p = ph[i];
    wr[i] = m * cosf(p);
    wi[i] = m * sinf(p);
}

// complex layernorm over last dim D=512; one block per row, 256 threads
__global__ __launch_bounds__(256) void cln_kernel(const float* __restrict__ xr,
                                                  const float* __restrict__ xi,
                                                  const float* __restrict__ gr,
                                                  const float* __restrict__ gi,
                                                  const float* __restrict__ br,
                                                  const float* __restrict__ bi,
                                                  float* __restrict__ outr,
                                                  float* __restrict__ outi) {
    int row = blockIdx.x;
    int t = threadIdx.x;
    const float* xrp = xr + (size_t)row * DM;
    const float* xip = xi + (size_t)row * DM;
    float a0 = xrp[t], a1 = xrp[t + 256];
    float b0 = xip[t], b1 = xip[t + 256];
    __shared__ float red[256];

    red[t] = a0 + a1; __syncthreads();
    for (int s2 = 128; s2 > 0; s2 >>= 1) { if (t < s2) red[t] += red[t + s2]; __syncthreads(); }
    float mr = red[0] * (1.0f / DM); __syncthreads();

    red[t] = b0 + b1; __syncthreads();
    for (int s2 = 128; s2 > 0; s2 >>= 1) { if (t < s2) red[t] += red[t + s2]; __syncthreads(); }
    float mi = red[0] * (1.0f / DM); __syncthreads();

    float c0 = a0 - mr, c1 = a1 - mr, d0 = b0 - mi, d1 = b1 - mi;
    red[t] = c0 * c0 + c1 * c1 + d0 * d0 + d1 * d1; __syncthreads();
    for (int s2 = 128; s2 > 0; s2 >>= 1) { if (t < s2) red[t] += red[t + s2]; __syncthreads(); }
    float inv = rsqrtf(red[0] * (1.0f / DM) + 1e-6f);

    float* orow = outr + (size_t)row * DM;
    float* oirow = outi + (size_t)row * DM;
    {
        float nr = c0 * inv, ni = d0 * inv;
        orow[t]  = nr * gr[t] - ni * gi[t] + br[t];
        oirow[t] = nr * gi[t] + ni * gr[t] + bi[t];
    }
    {
        int d_ = t + 256;
        float nr = c1 * inv, ni = d1 * inv;
        orow[d_]  = nr * gr[d_] - ni * gi[d_] + br[d_];
        oirow[d_] = nr * gi[d_] + ni * gr[d_] + bi[d_];
    }
}

// Complex GEMM:  Cr = Ar@Wr^T - Ai@Wi^T + bias_r ; Ci = Ar@Wi^T + Ai@Wr^T + bias_i
// A: (M,K) row-major; W: (N,K) row-major; C: (M,N)
// bias_r[n] = bm[n]*cos(bp[n]), bias_i[n] = bm[n]*sin(bp[n]) (bm may be null)
// Tiles: BM=BN=64, BK=16, block(16,16), 4x4 per thread. All dims divisible.
__global__ __launch_bounds__(256) void cgemm_kernel(const float* __restrict__ Ar,
                                                    const float* __restrict__ Ai,
                                                    const float* __restrict__ Wr,
                                                    const float* __restrict__ Wi,
                                                    const float* __restrict__ bm,
                                                    const float* __restrict__ bp,
                                                    float* __restrict__ Cr,
                                                    float* __restrict__ Ci,
                                                    int M, int N, int K) {
    __shared__ float sAr[16][64], sAi[16][64], sWr[16][64], sWi[16][64];
    int m0 = blockIdx.y * 64, n0 = blockIdx.x * 64;
    int tx = threadIdx.x, ty = threadIdx.y;
    int tid = ty * 16 + tx;
    float accR[4][4] = {{0}}, accI[4][4] = {{0}};

    for (int k0 = 0; k0 < K; k0 += 16) {
        #pragma unroll
        for (int l = 0; l < 4; l++) {
            int idx = tid + l * 256;
            int r = idx >> 4, c = idx & 15;
            sAr[c][r] = Ar[(size_t)(m0 + r) * K + k0 + c];
            sAi[c][r] = Ai[(size_t)(m0 + r) * K + k0 + c];
            sWr[c][r] = Wr[(size_t)(n0 + r) * K + k0 + c];
            sWi[c][r] = Wi[(size_t)(n0 + r) * K + k0 + c];
        }
        __syncthreads();
        #pragma unroll
        for (int kk = 0; kk < 16; kk++) {
            float ar[4], ai[4], wr[4], wi[4];
            #pragma unroll
            for (int j = 0; j < 4; j++) {
                ar[j] = sAr[kk][ty * 4 + j];
                ai[j] = sAi[kk][ty * 4 + j];
                wr[j] = sWr[kk][tx * 4 + j];
                wi[j] = sWi[kk][tx * 4 + j];
            }
            #pragma unroll
            for (int i2 = 0; i2 < 4; i2++)
                #pragma unroll
                for (int j2 = 0; j2 < 4; j2++) {
                    accR[i2][j2] += ar[i2] * wr[j2];
                    accR[i2][j2] -= ai[i2] * wi[j2];
                    accI[i2][j2] += ar[i2] * wi[j2];
                    accI[i2][j2] += ai[i2] * wr[j2];
                }
        }
        __syncthreads();
    }

    float brv[4] = {0, 0, 0, 0}, biv[4] = {0, 0, 0, 0};
    if (bm) {
        #pragma unroll
        for (int j2 = 0; j2 < 4; j2++) {
            int n = n0 + tx * 4 + j2;
            float mb = bm[n], pb = bp[n];
            brv[j2] = mb * cosf(pb);
            biv[j2] = mb * sinf(pb);
        }
    }
    #pragma unroll
    for (int i2 = 0; i2 < 4; i2++) {
        size_t mrow = (size_t)(m0 + ty * 4 + i2) * N;
        #pragma unroll
        for (int j2 = 0; j2 < 4; j2++) {
            int n = n0 + tx * 4 + j2;
            Cr[mrow + n] = accR[i2][j2] + brv[j2];
            Ci[mrow + n] = accI[i2][j2] + biv[j2];
        }
    }
}

// RoPE in place on q,k (real & imag). One thread per (b,h,s,j) pair, j<HD/2.
// Angles up to 1023 rad -> double sincos for accuracy (fast-math safe).
__global__ __launch_bounds__(256) void rope_kernel(float* __restrict__ qr, float* __restrict__ qi,
                                                   float* __restrict__ kr, float* __restrict__ ki) {
    int idx = blockIdx.x * 256 + threadIdx.x;   // < B*H*S*32 = 1048576
    int j = idx & 31;
    int s = (idx >> 5) & 1023;
    int h = (idx >> 15) & 7;
    int b = idx >> 18;
    double invf = pow(10000.0, -(double)(2 * j) / 64.0);
    double ang = (double)s * invf;
    double sd, cd;
    sincos(ang, &sd, &cd);
    float sn = (float)sd, cs = (float)cd;
    size_t base = (((size_t)b * SS + s) * DM) + h * HDD + j;
    float x0, x1;
    x0 = qr[base]; x1 = qr[base + 32]; qr[base] = x0 * cs - x1 * sn; qr[base + 32] = x1 * cs + x0 * sn;
    x0 = qi[base]; x1 = qi[base + 32]; qi[base] = x0 * cs - x1 * sn; qi[base + 32] = x1 * cs + x0 * sn;
    x0 = kr[base]; x1 = kr[base + 32]; kr[base] = x0 * cs - x1 * sn; kr[base + 32] = x1 * cs + x0 * sn;
    x0 = ki[base]; x1 = ki[base + 32]; ki[base] = x0 * cs - x1 * sn; ki[base + 32] = x1 * cs + x0 * sn;
}

// scores[bh, m, n] = (qr.kr + qi.ki)*scale ; only tiles with nt<=mt (causal)
__global__ __launch_bounds__(256) void scores_kernel(const float* __restrict__ qr,
                                                     const float* __restrict__ qi,
                                                     const float* __restrict__ kr,
                                                     const float* __restrict__ ki,
                                                     float* __restrict__ sc) {
    int bh = blockIdx.x, mt = blockIdx.y, nt = blockIdx.z;
    if (nt > mt) return;
    int b = bh >> 3, h = bh & 7;
    __shared__ float sQr[16][64], sQi[16][64], sKr[16][64], sKi[16][64];
    int m0 = mt * 64, n0 = nt * 64;
    int tx = threadIdx.x, ty = threadIdx.y;
    int tid = ty * 16 + tx;
    const size_t head_off = (size_t)b * SS * DM + (size_t)h * HDD;
    float acc[4][4] = {{0}};
    for (int k0 = 0; k0 < HDD; k0 += 16) {
        #pragma unroll
        for (int l = 0; l < 4; l++) {
            int idx = tid + l * 256;
            int r = idx >> 4, c = idx & 15;
            sQr[c][r] = qr[head_off + (size_t)(m0 + r) * DM + k0 + c];
            sQi[c][r] = qi[head_off + (size_t)(m0 + r) * DM + k0 + c];
            sKr[c][r] = kr[head_off + (size_t)(n0 + r) * DM + k0 + c];
            sKi[c][r] = ki[head_off + (size_t)(n0 + r) * DM + k0 + c];
        }
        __syncthreads();
        #pragma unroll
        for (int kk = 0; kk < 16; kk++) {
            float a[4], b2[4], c2[4], d2[4];
            #pragma unroll
            for (int j = 0; j < 4; j++) {
                a[j] = sQr[kk][ty * 4 + j];
                b2[j] = sQi[kk][ty * 4 + j];
                c2[j] = sKr[kk][tx * 4 + j];
                d2[j] = sKi[kk][tx * 4 + j];
            }
            #pragma unroll
            for (int i2 = 0; i2 < 4; i2++)
                #pragma unroll
                for (int j2 = 0; j2 < 4; j2++) {
                    acc[i2][j2] += a[i2] * c2[j2];
                    acc[i2][j2] += b2[i2] * d2[j2];
                }
        }
        __syncthreads();
    }
    const float scale = 0.125f;  // 1/sqrt(64)
    #pragma unroll
    for (int i2 = 0; i2 < 4; i2++) {
        size_t row = ((size_t)bh * SS + m0 + ty * 4 + i2) * SS;
        #pragma unroll
        for (int j2 = 0; j2 < 4; j2++)
            sc[row + n0 + tx * 4 + j2] = acc[i2][j2] * scale;
    }
}

// causal softmax per row; writes probs for col<=q, zeros for col>q
__global__ __launch_bounds__(256) void softmax_kernel(float* __restrict__ sc) {
    int row = blockIdx.x;          // bh*1024 + q
    int q = row & 1023;
    float* p = sc + (size_t)row * SS;
    int n = q + 1;
    int t = threadIdx.x;
    __shared__ float red[256];

    float mx = -1e30f;
    for (int i = t; i < n; i += 256) mx = fmaxf(mx, p[i]);
    red[t] = mx; __syncthreads();
    for (int s2 = 128; s2 > 0; s2 >>= 1) { if (t < s2) red[t] = fmaxf(red[t], red[t + s2]); __syncthreads(); }
    mx = red[0]; __syncthreads();

    float sum = 0.f;
    for (int i = t; i < n; i += 256) { float e = __expf(p[i] - mx); p[i] = e; sum += e; }
    red[t] = sum; __syncthreads();
    for (int s2 = 128; s2 > 0; s2 >>= 1) { if (t < s2) red[t] += red[t + s2]; __syncthreads(); }
    float inv = 1.0f / red[0];

    for (int i = t; i < n; i += 256) p[i] *= inv;
    for (int i = n + t; i < SS; i += 256) p[i] = 0.f;
}

// out[b, m, h*64+n] = sum_k attn[bh,m,k] * v[b,k,h*64+n]  (r and i)
__global__ __launch_bounds__(256) void av_kernel(const float* __restrict__ attn,
                                                 const float* __restrict__ vr,
                                                 const float* __restrict__ vi,
                                                 float* __restrict__ ar_out,
                                                 float* __restrict__ ai_out) {
    int bh = blockIdx.x, mt = blockIdx.y;
    int b = bh >> 3, h = bh & 7;
    __shared__ float sP[16][64], sVr[16][64], sVi[16][64];
    int m0 = mt * 64;
    int tx = threadIdx.x, ty = threadIdx.y;
    int tid = ty * 16 + tx;
    float accR[4][4] = {{0}}, accI[4][4] = {{0}};
    const size_t vbase = (size_t)b * SS * DM + (size_t)h * HDD;
    int kmax = m0 + 64;  // causal: tail zeros anyway
    for (int k0 = 0; k0 < kmax; k0 += 16) {
        {
            #pragma unroll
            for (int l = 0; l < 4; l++) {
                int idx = tid + l * 256;
                int r = idx >> 4, c = idx & 15;
                sP[c][r] = attn[((size_t)bh * SS + m0 + r) * SS + k0 + c];
                int kk = idx >> 6, nn = idx & 63;
                sVr[kk][nn] = vr[vbase + (size_t)(k0 + kk) * DM + nn];
                sVi[kk][nn] = vi[vbase + (size_t)(k0 + kk) * DM + nn];
            }
        }
        __syncthreads();
        #pragma unroll
        for (int kk = 0; kk < 16; kk++) {
            float pf[4], vrf[4], vif[4];
            #pragma unroll
            for (int j = 0; j < 4; j++) {
                pf[j] = sP[kk][ty * 4 + j];
                vrf[j] = sVr[kk][tx * 4 + j];
                vif[j] = sVi[kk][tx * 4 + j];
            }
            #pragma unroll
            for (int i2 = 0; i2 < 4; i2++)
                #pragma unroll
                for (int j2 = 0; j2 < 4; j2++) {
                    accR[i2][j2] += pf[i2] * vrf[j2];
                    accI[i2][j2] += pf[i2] * vif[j2];
                }
        }
        __syncthreads();
    }
    #pragma unroll
    for (int i2 = 0; i2 < 4; i2++) {
        size_t orow = (size_t)b * SS * DM + (size_t)(m0 + ty * 4 + i2) * DM + h * HDD;
        #pragma unroll
        for (int j2 = 0; j2 < 4; j2++) {
            ar_out[orow + tx * 4 + j2] = accR[i2][j2];
            ai_out[orow + tx * 4 + j2] = accI[i2][j2];
        }
    }
}

__global__ __launch_bounds__(256) void resid_kernel(const float* __restrict__ xr,
                                                    const float* __restrict__ xi,
                                                    const float* __restrict__ ar,
                                                    const float* __restrict__ ai,
                                                    float* __restrict__ out) {
    size_t i = (size_t)blockIdx.x * 256 + threadIdx.x;
    out[i] = xr[i] + ar[i];
    out[NDE + i] = xi[i] + ai[i];
}

__global__ __launch_bounds__(256) void gateact_kernel(float* __restrict__ gr, float* __restrict__ gi,
                                                      const float* __restrict__ ur,
                                                      const float* __restrict__ ui) {
    size_t i = (size_t)blockIdx.x * 256 + threadIdx.x;
    float a = gr[i], b = gi[i];
    float mag = sqrtf(a * a + b * b);
    float s = 1.0f / (1.0f + expf(-mag));
    float gar = a * s, gai = b * s;
    float u = ur[i], v = ui[i];
    gr[i] = gar * u - gai * v;
    gi[i] = gar * v + gai * u;
}

__global__ __launch_bounds__(256) void addout_kernel(const float* __restrict__ dr,
                                                     const float* __restrict__ di,
                                                     float* __restrict__ out) {
    size_t i = (size_t)blockIdx.x * 256 + threadIdx.x;
    out[i] += dr[i];
    out[NDE + i] += di[i];
}

// ---------------------------------------------------------------------------
extern "C" void kernel_launch(void* const* d_in, const int* in_sizes, int n_in,
                              void* d_out, int out_size) {
    const float* x_real = (const float*)d_in[0];
    const float* x_imag = (const float*)d_in[1];
    const float* ln1_gr = (const float*)d_in[2];
    const float* ln1_gi = (const float*)d_in[3];
    const float* ln1_br = (const float*)d_in[4];
    const float* ln1_bi = (const float*)d_in[5];
    const float* q_lm = (const float*)d_in[6];
    const float* q_ph = (const float*)d_in[7];
    const float* q_bm = (const float*)d_in[8];
    const float* q_bp = (const float*)d_in[9];
    const float* k_lm = (const float*)d_in[10];
    const float* k_ph = (const float*)d_in[11];
    const float* k_bm = (const float*)d_in[12];
    const float* k_bp = (const float*)d_in[13];
    const float* v_lm = (const float*)d_in[14];
    const float* v_ph = (const float*)d_in[15];
    const float* v_bm = (const float*)d_in[16];
    const float* v_bp = (const float*)d_in[17];
    const float* o_lm = (const float*)d_in[18];
    const float* o_ph = (const float*)d_in[19];
    const float* o_bm = (const float*)d_in[20];
    const float* o_bp = (const float*)d_in[21];
    const float* ln2_gr = (const float*)d_in[22];
    const float* ln2_gi = (const float*)d_in[23];
    const float* ln2_br = (const float*)d_in[24];
    const float* ln2_bi = (const float*)d_in[25];
    const float* gate_lm = (const float*)d_in[26];
    const float* gate_ph = (const float*)d_in[27];
    const float* up_lm = (const float*)d_in[28];
    const float* up_ph = (const float*)d_in[29];
    const float* down_lm = (const float*)d_in[30];
    const float* down_ph = (const float*)d_in[31];
    float* out = (float*)d_out;

    float* Sp = nullptr;
    cudaGetSymbolAddress((void**)&Sp, g_scratch);

    // scratch layout
    float* qwr = Sp;            float* qwi = qwr + DDE;
    float* kwr = qwi + DDE;     float* kwi = kwr + DDE;
    float* vwr = kwi + DDE;     float* vwi = vwr + DDE;
    float* owr = vwi + DDE;     float* owi = owr + DDE;
    float* gwr = owi + DDE;     float* gwi = gwr + GDE;
    float* uwr = gwi + GDE;     float* uwi = uwr + GDE;
    float* dwr = uwi + GDE;     float* dwi = dwr + GDE;
    float* hr = dwi + GDE;      float* hi = hr + NDE;
    float* qr = hi + NDE;       float* qi = qr + NDE;
    float* kr = qi + NDE;       float* ki = kr + NDE;
    float* vr = ki + NDE;       float* vi = vr + NDE;
    float* ar = vi + NDE;       float* ai = ar + NDE;
    float* gr = ai + NDE;       float* gi = gr + NHE;
    float* ur = gi + NHE;       float* ui = ur + NHE;
    float* sc = ui + NHE;

    dim3 blk2(16, 16);

    // 1) materialize weights W = exp(lm) * e^{i ph}
    make_w_kernel<<<(int)(DDE / 256), 256>>>(q_lm, q_ph, qwr, qwi, (int)DDE);
    make_w_kernel<<<(int)(DDE / 256), 256>>>(k_lm, k_ph, kwr, kwi, (int)DDE);
    make_w_kernel<<<(int)(DDE / 256), 256>>>(v_lm, v_ph, vwr, vwi, (int)DDE);
    make_w_kernel<<<(int)(DDE / 256), 256>>>(o_lm, o_ph, owr, owi, (int)DDE);
    make_w_kernel<<<(int)(GDE / 256), 256>>>(gate_lm, gate_ph, gwr, gwi, (int)GDE);
    make_w_kernel<<<(int)(GDE / 256), 256>>>(up_lm, up_ph, uwr, uwi, (int)GDE);
    make_w_kernel<<<(int)(GDE / 256), 256>>>(down_lm, down_ph, dwr, dwi, (int)GDE);

    // 2) LN1
    cln_kernel<<<NT, 256>>>(x_real, x_imag, ln1_gr, ln1_gi, ln1_br, ln1_bi, hr, hi);

    // 3) QKV projections
    cgemm_kernel<<<dim3(DM / 64, NT / 64), blk2>>>(hr, hi, qwr, qwi, q_bm, q_bp, qr, qi, NT, DM, DM);
    cgemm_kernel<<<dim3(DM / 64, NT / 64), blk2>>>(hr, hi, kwr, kwi, k_bm, k_bp, kr, ki, NT, DM, DM);
    cgemm_kernel<<<dim3(DM / 64, NT / 64), blk2>>>(hr, hi, vwr, vwi, v_bm, v_bp, vr, vi, NT, DM, DM);

    // 4) RoPE on q,k
    rope_kernel<<<(BB * HH * SS * (HDD / 2)) / 256, 256>>>(qr, qi, kr, ki);

    // 5) attention
    scores_kernel<<<dim3(BB * HH, SS / 64, SS / 64), blk2>>>(qr, qi, kr, ki, sc);
    softmax_kernel<<<BB * HH * SS, 256>>>(sc);
    av_kernel<<<dim3(BB * HH, SS / 64), blk2>>>(sc, vr, vi, ar, ai);

    // 6) output projection (reuse qr/qi as o-proj output)
    cgemm_kernel<<<dim3(DM / 64, NT / 64), blk2>>>(ar, ai, owr, owi, o_bm, o_bp, qr, qi, NT, DM, DM);

    // 7) residual -> d_out (res_r at [0..N), res_i at [N..2N))
    resid_kernel<<<(int)(NDE / 256), 256>>>(x_real, x_imag, qr, qi, out);

    // 8) LN2 (reads residual from d_out)
    cln_kernel<<<NT, 256>>>(out, out + NDE, ln2_gr, ln2_gi, ln2_br, ln2_bi, hr, hi);

    // 9) FFN
    cgemm_kernel<<<dim3(HIDD / 64, NT / 64), blk2>>>(hr, hi, gwr, gwi, nullptr, nullptr, gr, gi, NT, HIDD, DM);
    cgemm_kernel<<<dim3(HIDD / 64, NT / 64), blk2>>>(hr, hi, uwr, uwi, nullptr, nullptr, ur, ui, NT, HIDD, DM);
    gateact_kernel<<<(int)(NHE / 256), 256>>>(gr, gi, ur, ui);
    // down proj (reuse kr/ki as output)
    cgemm_kernel<<<dim3(DM / 64, NT / 64), blk2>>>(gr, gi, dwr, dwi, nullptr, nullptr, kr, ki, NT, DM, HIDD);

    // 10) final residual add into d_out
    addout_kernel<<<(int)(NDE / 256), 256>>>(kr, ki, out);
}

// round 6
// speedup vs baseline: 1.4385x; 1.4385x over previous
#include <cuda_runtime.h>
#include <math.h>

// Problem dims (fixed)
#define BB 4
#define SS 1024
#define DM 512
#define HH 8
#define HDD 64
#define HIDD 2048
#define NT (BB*SS)                 // 4096 token rows
#define NDE ((size_t)NT*DM)        // 2097152
#define NHE ((size_t)NT*HIDD)      // 8388608
#define DDE ((size_t)DM*DM)        // 262144
#define GDE ((size_t)HIDD*DM)      // 1048576

typedef unsigned long long ull;

// -------- scratch: one big __device__ array (no allocations allowed) --------
__device__ float g_scratch[96468992];

// ---- f32x2 packed helpers (FFMA2 path — ptxas won't auto-fuse; PTX only) ----
__device__ __forceinline__ ull pk2(float x) {
    ull r; asm("mov.b64 %0, {%1, %1};" : "=l"(r) : "f"(x)); return r;
}
__device__ __forceinline__ void fma2(ull &d, ull a, ull b) {
    asm("fma.rn.f32x2 %0, %1, %2, %0;" : "+l"(d) : "l"(a), "l"(b));
}
__device__ __forceinline__ float2 up2(ull v) {
    float2 f; asm("mov.b64 {%0, %1}, %2;" : "=f"(f.x), "=f"(f.y) : "l"(v)); return f;
}
#define NEGMASK 0x8000000080000000ULL

// ---------------------------------------------------------------------------
__global__ __launch_bounds__(256) void make_w_kernel(const float* __restrict__ lm,
                                                     const float* __restrict__ ph,
                                                     float* __restrict__ wr,
                                                     float* __restrict__ wi, int n) {
    int i = blockIdx.x * 256 + threadIdx.x;
    if (i >= n) return;
    float m = expf(lm[i]);
    float p = ph[i];
    wr[i] = m * cosf(p);
    wi[i] = m * sinf(p);
}

// complex layernorm over last dim D=512; one block per row, 256 threads
__global__ __launch_bounds__(256) void cln_kernel(const float* __restrict__ xr,
                                                  const float* __restrict__ xi,
                                                  const float* __restrict__ gr,
                                                  const float* __restrict__ gi,
                                                  const float* __restrict__ br,
                                                  const float* __restrict__ bi,
                                                  float* __restrict__ outr,
                                                  float* __restrict__ outi) {
    int row = blockIdx.x;
    int t = threadIdx.x;
    const float* xrp = xr + (size_t)row * DM;
    const float* xip = xi + (size_t)row * DM;
    float a0 = xrp[t], a1 = xrp[t + 256];
    float b0 = xip[t], b1 = xip[t + 256];
    __shared__ float red[256];

    red[t] = a0 + a1; __syncthreads();
    for (int s2 = 128; s2 > 0; s2 >>= 1) { if (t < s2) red[t] += red[t + s2]; __syncthreads(); }
    float mr = red[0] * (1.0f / DM); __syncthreads();

    red[t] = b0 + b1; __syncthreads();
    for (int s2 = 128; s2 > 0; s2 >>= 1) { if (t < s2) red[t] += red[t + s2]; __syncthreads(); }
    float mi = red[0] * (1.0f / DM); __syncthreads();

    float c0 = a0 - mr, c1 = a1 - mr, d0 = b0 - mi, d1 = b1 - mi;
    red[t] = c0 * c0 + c1 * c1 + d0 * d0 + d1 * d1; __syncthreads();
    for (int s2 = 128; s2 > 0; s2 >>= 1) { if (t < s2) red[t] += red[t + s2]; __syncthreads(); }
    float inv = rsqrtf(red[0] * (1.0f / DM) + 1e-6f);

    float* orow = outr + (size_t)row * DM;
    float* oirow = outi + (size_t)row * DM;
    {
        float nr = c0 * inv, ni = d0 * inv;
        orow[t]  = nr * gr[t] - ni * gi[t] + br[t];
        oirow[t] = nr * gi[t] + ni * gr[t] + bi[t];
    }
    {
        int d_ = t + 256;
        float nr = c1 * inv, ni = d1 * inv;
        orow[d_]  = nr * gr[d_] - ni * gi[d_] + br[d_];
        oirow[d_] = nr * gi[d_] + ni * gr[d_] + bi[d_];
    }
}

// Complex GEMM (FFMA2):  Cr = Ar@Wr^T - Ai@Wi^T + br ; Ci = Ar@Wi^T + Ai@Wr^T + bi
// A: (M,K) rm; W: (N,K) rm; C: (M,N). Tiles BM=64, BN=128, BK=16; block 16x16;
// per-thread 4(m) x 8(n), acc packed along n pairs. SMEM rows padded to break
// the fill-time STS bank conflict (68/132 floats per kk-row, 16B aligned).
__global__ __launch_bounds__(256, 2) void cgemm_kernel(const float* __restrict__ Ar,
                                                       const float* __restrict__ Ai,
                                                       const float* __restrict__ Wr,
                                                       const float* __restrict__ Wi,
                                                       const float* __restrict__ bm,
                                                       const float* __restrict__ bp,
                                                       float* __restrict__ Cr,
                                                       float* __restrict__ Ci,
                                                       int M, int N, int K) {
    __shared__ float sAr[16][68], sAi[16][68];
    __shared__ float sWr[16][132], sWi[16][132];
    int m0 = blockIdx.y * 64, n0 = blockIdx.x * 128;
    int tx = threadIdx.x, ty = threadIdx.y;
    int tid = ty * 16 + tx;

    ull accR[4][4], accI[4][4];
    #pragma unroll
    for (int i = 0; i < 4; i++)
        #pragma unroll
        for (int p = 0; p < 4; p++) { accR[i][p] = 0ULL; accI[i][p] = 0ULL; }

    for (int k0 = 0; k0 < K; k0 += 16) {
        #pragma unroll
        for (int l = 0; l < 4; l++) {
            int idx = tid + l * 256;              // 1024 = 64 x 16
            int r = idx >> 4, c = idx & 15;
            sAr[c][r] = Ar[(size_t)(m0 + r) * K + k0 + c];
            sAi[c][r] = Ai[(size_t)(m0 + r) * K + k0 + c];
        }
        #pragma unroll
        for (int l = 0; l < 8; l++) {
            int idx = tid + l * 256;              // 2048 = 128 x 16
            int r = idx >> 4, c = idx & 15;
            sWr[c][r] = Wr[(size_t)(n0 + r) * K + k0 + c];
            sWi[c][r] = Wi[(size_t)(n0 + r) * K + k0 + c];
        }
        __syncthreads();
        #pragma unroll
        for (int kk = 0; kk < 16; kk++) {
            float4 arv = *(const float4*)&sAr[kk][ty * 4];
            float4 aiv = *(const float4*)&sAi[kk][ty * 4];
            ulonglong2 wr01 = *(const ulonglong2*)&sWr[kk][tx * 8];
            ulonglong2 wr23 = *(const ulonglong2*)&sWr[kk][tx * 8 + 4];
            ulonglong2 wi01 = *(const ulonglong2*)&sWi[kk][tx * 8];
            ulonglong2 wi23 = *(const ulonglong2*)&sWi[kk][tx * 8 + 4];
            ull wr[4] = {wr01.x, wr01.y, wr23.x, wr23.y};
            ull wi[4] = {wi01.x, wi01.y, wi23.x, wi23.y};
            float as[4] = {arv.x, arv.y, arv.z, arv.w};
            float is[4] = {aiv.x, aiv.y, aiv.z, aiv.w};
            #pragma unroll
            for (int i = 0; i < 4; i++) {
                ull arP = pk2(as[i]);
                ull aiP = pk2(is[i]);
                ull naP = aiP ^ NEGMASK;
                #pragma unroll
                for (int p = 0; p < 4; p++) {
                    fma2(accR[i][p], arP, wr[p]);
                    fma2(accR[i][p], naP, wi[p]);
                    fma2(accI[i][p], arP, wi[p]);
                    fma2(accI[i][p], aiP, wr[p]);
                }
            }
        }
        __syncthreads();
    }

    float br8[8], bi8[8];
    #pragma unroll
    for (int j = 0; j < 8; j++) { br8[j] = 0.f; bi8[j] = 0.f; }
    if (bm) {
        #pragma unroll
        for (int j = 0; j < 8; j++) {
            int n = n0 + tx * 8 + j;
            float mb = bm[n], pb = bp[n];
            br8[j] = mb * cosf(pb);
            bi8[j] = mb * sinf(pb);
        }
    }
    #pragma unroll
    for (int i = 0; i < 4; i++) {
        size_t base = (size_t)(m0 + ty * 4 + i) * N + n0 + tx * 8;
        float2 r0 = up2(accR[i][0]), r1 = up2(accR[i][1]);
        float2 r2 = up2(accR[i][2]), r3 = up2(accR[i][3]);
        float2 q0 = up2(accI[i][0]), q1 = up2(accI[i][1]);
        float2 q2 = up2(accI[i][2]), q3 = up2(accI[i][3]);
        float4 o0 = make_float4(r0.x + br8[0], r0.y + br8[1], r1.x + br8[2], r1.y + br8[3]);
        float4 o1 = make_float4(r2.x + br8[4], r2.y + br8[5], r3.x + br8[6], r3.y + br8[7]);
        float4 o2 = make_float4(q0.x + bi8[0], q0.y + bi8[1], q1.x + bi8[2], q1.y + bi8[3]);
        float4 o3 = make_float4(q2.x + bi8[4], q2.y + bi8[5], q3.x + bi8[6], q3.y + bi8[7]);
        *(float4*)&Cr[base] = o0;
        *(float4*)&Cr[base + 4] = o1;
        *(float4*)&Ci[base] = o2;
        *(float4*)&Ci[base + 4] = o3;
    }
}

// RoPE in place on q,k (real & imag). Angles up to 1023 rad -> double sincos.
__global__ __launch_bounds__(256) void rope_kernel(float* __restrict__ qr, float* __restrict__ qi,
                                                   float* __restrict__ kr, float* __restrict__ ki) {
    int idx = blockIdx.x * 256 + threadIdx.x;   // < B*H*S*32 = 1048576
    int j = idx & 31;
    int s = (idx >> 5) & 1023;
    int h = (idx >> 15) & 7;
    int b = idx >> 18;
    double invf = pow(10000.0, -(double)(2 * j) / 64.0);
    double ang = (double)s * invf;
    double sd, cd;
    sincos(ang, &sd, &cd);
    float sn = (float)sd, cs = (float)cd;
    size_t base = (((size_t)b * SS + s) * DM) + h * HDD + j;
    float x0, x1;
    x0 = qr[base]; x1 = qr[base + 32]; qr[base] = x0 * cs - x1 * sn; qr[base + 32] = x1 * cs + x0 * sn;
    x0 = qi[base]; x1 = qi[base + 32]; qi[base] = x0 * cs - x1 * sn; qi[base + 32] = x1 * cs + x0 * sn;
    x0 = kr[base]; x1 = kr[base + 32]; kr[base] = x0 * cs - x1 * sn; kr[base + 32] = x1 * cs + x0 * sn;
    x0 = ki[base]; x1 = ki[base + 32]; ki[base] = x0 * cs - x1 * sn; ki[base + 32] = x1 * cs + x0 * sn;
}

// scores[bh, m, n] = (qr.kr + qi.ki)*scale ; only tiles with nt<=mt (causal)
__global__ __launch_bounds__(256) void scores_kernel(const float* __restrict__ qr,
                                                     const float* __restrict__ qi,
                                                     const float* __restrict__ kr,
                                                     const float* __restrict__ ki,
                                                     float* __restrict__ sc) {
    int bh = blockIdx.x, mt = blockIdx.y, nt = blockIdx.z;
    if (nt > mt) return;
    int b = bh >> 3, h = bh & 7;
    __shared__ float sQr[16][64], sQi[16][64], sKr[16][64], sKi[16][64];
    int m0 = mt * 64, n0 = nt * 64;
    int tx = threadIdx.x, ty = threadIdx.y;
    int tid = ty * 16 + tx;
    const size_t head_off = (size_t)b * SS * DM + (size_t)h * HDD;
    float acc[4][4] = {{0}};
    for (int k0 = 0; k0 < HDD; k0 += 16) {
        #pragma unroll
        for (int l = 0; l < 4; l++) {
            int idx = tid + l * 256;
            int r = idx >> 4, c = idx & 15;
            sQr[c][r] = qr[head_off + (size_t)(m0 + r) * DM + k0 + c];
            sQi[c][r] = qi[head_off + (size_t)(m0 + r) * DM + k0 + c];
            sKr[c][r] = kr[head_off + (size_t)(n0 + r) * DM + k0 + c];
            sKi[c][r] = ki[head_off + (size_t)(n0 + r) * DM + k0 + c];
        }
        __syncthreads();
        #pragma unroll
        for (int kk = 0; kk < 16; kk++) {
            float a[4], b2[4], c2[4], d2[4];
            #pragma unroll
            for (int j = 0; j < 4; j++) {
                a[j] = sQr[kk][ty * 4 + j];
                b2[j] = sQi[kk][ty * 4 + j];
                c2[j] = sKr[kk][tx * 4 + j];
                d2[j] = sKi[kk][tx * 4 + j];
            }
            #pragma unroll
            for (int i2 = 0; i2 < 4; i2++)
                #pragma unroll
                for (int j2 = 0; j2 < 4; j2++) {
                    acc[i2][j2] += a[i2] * c2[j2];
                    acc[i2][j2] += b2[i2] * d2[j2];
                }
        }
        __syncthreads();
    }
    const float scale = 0.125f;  // 1/sqrt(64)
    #pragma unroll
    for (int i2 = 0; i2 < 4; i2++) {
        size_t row = ((size_t)bh * SS + m0 + ty * 4 + i2) * SS;
        #pragma unroll
        for (int j2 = 0; j2 < 4; j2++)
            sc[row + n0 + tx * 4 + j2] = acc[i2][j2] * scale;
    }
}

// causal softmax per row; writes probs for col<=q, zeros for col>q
__global__ __launch_bounds__(256) void softmax_kernel(float* __restrict__ sc) {
    int row = blockIdx.x;          // bh*1024 + q
    int q = row & 1023;
    float* p = sc + (size_t)row * SS;
    int n = q + 1;
    int t = threadIdx.x;
    __shared__ float red[256];

    float mx = -1e30f;
    for (int i = t; i < n; i += 256) mx = fmaxf(mx, p[i]);
    red[t] = mx; __syncthreads();
    for (int s2 = 128; s2 > 0; s2 >>= 1) { if (t < s2) red[t] = fmaxf(red[t], red[t + s2]); __syncthreads(); }
    mx = red[0]; __syncthreads();

    float sum = 0.f;
    for (int i = t; i < n; i += 256) { float e = __expf(p[i] - mx); p[i] = e; sum += e; }
    red[t] = sum; __syncthreads();
    for (int s2 = 128; s2 > 0; s2 >>= 1) { if (t < s2) red[t] += red[t + s2]; __syncthreads(); }
    float inv = 1.0f / red[0];

    for (int i = t; i < n; i += 256) p[i] *= inv;
    for (int i = n + t; i < SS; i += 256) p[i] = 0.f;
}

// out[b, m, h*64+n] = sum_k attn[bh,m,k] * v[b,k,h*64+n]  (r and i), FFMA2
__global__ __launch_bounds__(256) void av_kernel(const float* __restrict__ attn,
                                                 const float* __restrict__ vr,
                                                 const float* __restrict__ vi,
                                                 float* __restrict__ ar_out,
                                                 float* __restrict__ ai_out) {
    int bh = blockIdx.x, mt = blockIdx.y;
    int b = bh >> 3, h = bh & 7;
    __shared__ float sP[16][64], sVr[16][64], sVi[16][64];
    int m0 = mt * 64;
    int tx = threadIdx.x, ty = threadIdx.y;
    int tid = ty * 16 + tx;
    ull accR[4][2], accI[4][2];
    #pragma unroll
    for (int i = 0; i < 4; i++) { accR[i][0] = accR[i][1] = 0ULL; accI[i][0] = accI[i][1] = 0ULL; }
    const size_t vbase = (size_t)b * SS * DM + (size_t)h * HDD;
    int kmax = m0 + 64;  // causal: tail zeros anyway
    for (int k0 = 0; k0 < kmax; k0 += 16) {
        #pragma unroll
        for (int l = 0; l < 4; l++) {
            int idx = tid + l * 256;
            int r = idx >> 4, c = idx & 15;
            sP[c][r] = attn[((size_t)bh * SS + m0 + r) * SS + k0 + c];
            int kk = idx >> 6, nn = idx & 63;
            sVr[kk][nn] = vr[vbase + (size_t)(k0 + kk) * DM + nn];
            sVi[kk][nn] = vi[vbase + (size_t)(k0 + kk) * DM + nn];
        }
        __syncthreads();
        #pragma unroll
        for (int kk = 0; kk < 16; kk++) {
            float4 pv = *(const float4*)&sP[kk][ty * 4];
            ulonglong2 vr2 = *(const ulonglong2*)&sVr[kk][tx * 4];
            ulonglong2 vi2 = *(const ulonglong2*)&sVi[kk][tx * 4];
            float ps[4] = {pv.x, pv.y, pv.z, pv.w};
            ull vrp[2] = {vr2.x, vr2.y};
            ull vip[2] = {vi2.x, vi2.y};
            #pragma unroll
            for (int i = 0; i < 4; i++) {
                ull pP = pk2(ps[i]);
                #pragma unroll
                for (int p = 0; p < 2; p++) {
                    fma2(accR[i][p], pP, vrp[p]);
                    fma2(accI[i][p], pP, vip[p]);
                }
            }
        }
        __syncthreads();
    }
    #pragma unroll
    for (int i = 0; i < 4; i++) {
        size_t orow = (size_t)b * SS * DM + (size_t)(m0 + ty * 4 + i) * DM + h * HDD + tx * 4;
        float2 r0 = up2(accR[i][0]), r1 = up2(accR[i][1]);
        float2 q0 = up2(accI[i][0]), q1 = up2(accI[i][1]);
        *(float4*)&ar_out[orow] = make_float4(r0.x, r0.y, r1.x, r1.y);
        *(float4*)&ai_out[orow] = make_float4(q0.x, q0.y, q1.x, q1.y);
    }
}

__global__ __launch_bounds__(256) void resid_kernel(const float* __restrict__ xr,
                                                    const float* __restrict__ xi,
                                                    const float* __restrict__ ar,
                                                    const float* __restrict__ ai,
                                                    float* __restrict__ out) {
    size_t i = (size_t)blockIdx.x * 256 + threadIdx.x;
    out[i] = xr[i] + ar[i];
    out[NDE + i] = xi[i] + ai[i];
}

__global__ __launch_bounds__(256) void gateact_kernel(float* __restrict__ gr, float* __restrict__ gi,
                                                      const float* __restrict__ ur,
                                                      const float* __restrict__ ui) {
    size_t i = (size_t)blockIdx.x * 256 + threadIdx.x;
    float a = gr[i], b = gi[i];
    float mag = sqrtf(a * a + b * b);
    float s = 1.0f / (1.0f + expf(-mag));
    float gar = a * s, gai = b * s;
    float u = ur[i], v = ui[i];
    gr[i] = gar * u - gai * v;
    gi[i] = gar * v + gai * u;
}

__global__ __launch_bounds__(256) void addout_kernel(const float* __restrict__ dr,
                                                     const float* __restrict__ di,
                                                     float* __restrict__ out) {
    size_t i = (size_t)blockIdx.x * 256 + threadIdx.x;
    out[i] += dr[i];
    out[NDE + i] += di[i];
}

// ---------------------------------------------------------------------------
extern "C" void kernel_launch(void* const* d_in, const int* in_sizes, int n_in,
                              void* d_out, int out_size) {
    const float* x_real = (const float*)d_in[0];
    const float* x_imag = (const float*)d_in[1];
    const float* ln1_gr = (const float*)d_in[2];
    const float* ln1_gi = (const float*)d_in[3];
    const float* ln1_br = (const float*)d_in[4];
    const float* ln1_bi = (const float*)d_in[5];
    const float* q_lm = (const float*)d_in[6];
    const float* q_ph = (const float*)d_in[7];
    const float* q_bm = (const float*)d_in[8];
    const float* q_bp = (const float*)d_in[9];
    const float* k_lm = (const float*)d_in[10];
    const float* k_ph = (const float*)d_in[11];
    const float* k_bm = (const float*)d_in[12];
    const float* k_bp = (const float*)d_in[13];
    const float* v_lm = (const float*)d_in[14];
    const float* v_ph = (const float*)d_in[15];
    const float* v_bm = (const float*)d_in[16];
    const float* v_bp = (const float*)d_in[17];
    const float* o_lm = (const float*)d_in[18];
    const float* o_ph = (const float*)d_in[19];
    const float* o_bm = (const float*)d_in[20];
    const float* o_bp = (const float*)d_in[21];
    const float* ln2_gr = (const float*)d_in[22];
    const float* ln2_gi = (const float*)d_in[23];
    const float* ln2_br = (const float*)d_in[24];
    const float* ln2_bi = (const float*)d_in[25];
    const float* gate_lm = (const float*)d_in[26];
    const float* gate_ph = (const float*)d_in[27];
    const float* up_lm = (const float*)d_in[28];
    const float* up_ph = (const float*)d_in[29];
    const float* down_lm = (const float*)d_in[30];
    const float* down_ph = (const float*)d_in[31];
    float* out = (float*)d_out;

    float* Sp = nullptr;
    cudaGetSymbolAddress((void**)&Sp, g_scratch);

    // scratch layout
    float* qwr = Sp;            float* qwi = qwr + DDE;
    float* kwr = qwi + DDE;     float* kwi = kwr + DDE;
    float* vwr = kwi + DDE;     float* vwi = vwr + DDE;
    float* owr = vwi + DDE;     float* owi = owr + DDE;
    float* gwr = owi + DDE;     float* gwi = gwr + GDE;
    float* uwr = gwi + GDE;     float* uwi = uwr + GDE;
    float* dwr = uwi + GDE;     float* dwi = dwr + GDE;
    float* hr = dwi + GDE;      float* hi = hr + NDE;
    float* qr = hi + NDE;       float* qi = qr + NDE;
    float* kr = qi + NDE;       float* ki = kr + NDE;
    float* vr = ki + NDE;       float* vi = vr + NDE;
    float* ar = vi + NDE;       float* ai = ar + NDE;
    float* gr = ai + NDE;       float* gi = gr + NHE;
    float* ur = gi + NHE;       float* ui = ur + NHE;
    float* sc = ui + NHE;

    dim3 blk2(16, 16);

    // 1) materialize weights W = exp(lm) * e^{i ph}
    make_w_kernel<<<(int)(DDE / 256), 256>>>(q_lm, q_ph, qwr, qwi, (int)DDE);
    make_w_kernel<<<(int)(DDE / 256), 256>>>(k_lm, k_ph, kwr, kwi, (int)DDE);
    make_w_kernel<<<(int)(DDE / 256), 256>>>(v_lm, v_ph, vwr, vwi, (int)DDE);
    make_w_kernel<<<(int)(DDE / 256), 256>>>(o_lm, o_ph, owr, owi, (int)DDE);
    make_w_kernel<<<(int)(GDE / 256), 256>>>(gate_lm, gate_ph, gwr, gwi, (int)GDE);
    make_w_kernel<<<(int)(GDE / 256), 256>>>(up_lm, up_ph, uwr, uwi, (int)GDE);
    make_w_kernel<<<(int)(GDE / 256), 256>>>(down_lm, down_ph, dwr, dwi, (int)GDE);

    // 2) LN1
    cln_kernel<<<NT, 256>>>(x_real, x_imag, ln1_gr, ln1_gi, ln1_br, ln1_bi, hr, hi);

    // 3) QKV projections (BN=128 tiles)
    cgemm_kernel<<<dim3(DM / 128, NT / 64), blk2>>>(hr, hi, qwr, qwi, q_bm, q_bp, qr, qi, NT, DM, DM);
    cgemm_kernel<<<dim3(DM / 128, NT / 64), blk2>>>(hr, hi, kwr, kwi, k_bm, k_bp, kr, ki, NT, DM, DM);
    cgemm_kernel<<<dim3(DM / 128, NT / 64), blk2>>>(hr, hi, vwr, vwi, v_bm, v_bp, vr, vi, NT, DM, DM);

    // 4) RoPE on q,k
    rope_kernel<<<(BB * HH * SS * (HDD / 2)) / 256, 256>>>(qr, qi, kr, ki);

    // 5) attention
    scores_kernel<<<dim3(BB * HH, SS / 64, SS / 64), blk2>>>(qr, qi, kr, ki, sc);
    softmax_kernel<<<BB * HH * SS, 256>>>(sc);
    av_kernel<<<dim3(BB * HH, SS / 64), blk2>>>(sc, vr, vi, ar, ai);

    // 6) output projection (reuse qr/qi as o-proj output)
    cgemm_kernel<<<dim3(DM / 128, NT / 64), blk2>>>(ar, ai, owr, owi, o_bm, o_bp, qr, qi, NT, DM, DM);

    // 7) residual -> d_out (res_r at [0..N), res_i at [N..2N))
    resid_kernel<<<(int)(NDE / 256), 256>>>(x_real, x_imag, qr, qi, out);

    // 8) LN2 (reads residual from d_out)
    cln_kernel<<<NT, 256>>>(out, out + NDE, ln2_gr, ln2_gi, ln2_br, ln2_bi, hr, hi);

    // 9) FFN
    cgemm_kernel<<<dim3(HIDD / 128, NT / 64), blk2>>>(hr, hi, gwr, gwi, nullptr, nullptr, gr, gi, NT, HIDD, DM);
    cgemm_kernel<<<dim3(HIDD / 128, NT / 64), blk2>>>(hr, hi, uwr, uwi, nullptr, nullptr, ur, ui, NT, HIDD, DM);
    gateact_kernel<<<(int)(NHE / 256), 256>>>(gr, gi, ur, ui);
    // down proj (reuse kr/ki as output)
    cgemm_kernel<<<dim3(DM / 128, NT / 64), blk2>>>(gr, gi, dwr, dwi, nullptr, nullptr, kr, ki, NT, DM, HIDD);

    // 10) final residual add into d_out
    addout_kernel<<<(int)(NDE / 256), 256>>>(kr, ki, out);
}

// round 8
// speedup vs baseline: 2.9935x; 2.0811x over previous
#include <cuda_runtime.h>
#include <math.h>

// Problem dims (fixed)
#define BB 4
#define SS 1024
#define DM 512
#define HH 8
#define HDD 64
#define HIDD 2048
#define NT (BB*SS)                 // 4096 token rows
#define NDE ((size_t)NT*DM)        // 2097152
#define NHE ((size_t)NT*HIDD)      // 8388608
#define DDE ((size_t)DM*DM)        // 262144
#define GDE ((size_t)HIDD*DM)      // 1048576

typedef unsigned long long ull;
typedef unsigned int uint32;

// -------- scratch: one big __device__ array (no allocations allowed) --------
__device__ float g_scratch[96468992];

// ---- f32x2 packed helpers (FFMA2 path — attention kernels) ----
__device__ __forceinline__ ull pk2(float x) {
    ull r; asm("mov.b64 %0, {%1, %1};" : "=l"(r) : "f"(x)); return r;
}
__device__ __forceinline__ void fma2(ull &d, ull a, ull b) {
    asm("fma.rn.f32x2 %0, %1, %2, %0;" : "+l"(d) : "l"(a), "l"(b));
}
__device__ __forceinline__ float2 up2(ull v) {
    float2 f; asm("mov.b64 {%0, %1}, %2;" : "=f"(f.x), "=f"(f.y) : "l"(v)); return f;
}

// ---- tf32 helpers ----
__device__ __forceinline__ uint32 to_tf32(float x) {
    uint32 r; asm("cvt.rna.tf32.f32 %0, %1;" : "=r"(r) : "f"(x)); return r;
}
#define MMA_TF32(d, a, b) \
    asm volatile("mma.sync.aligned.m16n8k8.row.col.f32.tf32.tf32.f32 " \
                 "{%0,%1,%2,%3}, {%4,%5,%6,%7}, {%8,%9}, {%0,%1,%2,%3};" \
                 : "+f"(d[0]), "+f"(d[1]), "+f"(d[2]), "+f"(d[3]) \
                 : "r"(a[0]), "r"(a[1]), "r"(a[2]), "r"(a[3]), "r"(b[0]), "r"(b[1]))

// ---------------------------------------------------------------------------
__global__ __launch_bounds__(256) void make_w_kernel(const float* __restrict__ lm,
                                                     const float* __restrict__ ph,
                                                     float* __restrict__ wr,
                                                     float* __restrict__ wi, int n) {
    int i = blockIdx.x * 256 + threadIdx.x;
    if (i >= n) return;
    float m = expf(lm[i]);
    float p = ph[i];
    wr[i] = m * cosf(p);
    wi[i] = m * sinf(p);
}

// complex layernorm over last dim D=512; one block per row, 256 threads
__global__ __launch_bounds__(256) void cln_kernel(const float* __restrict__ xr,
                                                  const float* __restrict__ xi,
                                                  const float* __restrict__ gr,
                                                  const float* __restrict__ gi,
                                                  const float* __restrict__ br,
                                                  const float* __restrict__ bi,
                                                  float* __restrict__ outr,
                                                  float* __restrict__ outi) {
    int row = blockIdx.x;
    int t = threadIdx.x;
    const float* xrp = xr + (size_t)row * DM;
    const float* xip = xi + (size_t)row * DM;
    float a0 = xrp[t], a1 = xrp[t + 256];
    float b0 = xip[t], b1 = xip[t + 256];
    __shared__ float red[256];

    red[t] = a0 + a1; __syncthreads();
    for (int s2 = 128; s2 > 0; s2 >>= 1) { if (t < s2) red[t] += red[t + s2]; __syncthreads(); }
    float mr = red[0] * (1.0f / DM); __syncthreads();

    red[t] = b0 + b1; __syncthreads();
    for (int s2 = 128; s2 > 0; s2 >>= 1) { if (t < s2) red[t] += red[t + s2]; __syncthreads(); }
    float mi = red[0] * (1.0f / DM); __syncthreads();

    float c0 = a0 - mr, c1 = a1 - mr, d0 = b0 - mi, d1 = b1 - mi;
    red[t] = c0 * c0 + c1 * c1 + d0 * d0 + d1 * d1; __syncthreads();
    for (int s2 = 128; s2 > 0; s2 >>= 1) { if (t < s2) red[t] += red[t + s2]; __syncthreads(); }
    float inv = rsqrtf(red[0] * (1.0f / DM) + 1e-6f);

    float* orow = outr + (size_t)row * DM;
    float* oirow = outi + (size_t)row * DM;
    {
        float nr = c0 * inv, ni = d0 * inv;
        orow[t]  = nr * gr[t] - ni * gi[t] + br[t];
        oirow[t] = nr * gi[t] + ni * gr[t] + bi[t];
    }
    {
        int d_ = t + 256;
        float nr = c1 * inv, ni = d1 * inv;
        orow[d_]  = nr * gr[d_] - ni * gi[d_] + br[d_];
        oirow[d_] = nr * gi[d_] + ni * gr[d_] + bi[d_];
    }
}

// ============================================================================
// Tensor-core complex GEMM (tf32 mma.sync m16n8k8):
//   Cr = Ar@Wr^T - Ai@Wi^T + br ; Ci = Ar@Wi^T + Ai@Wr^T + bi
// A: (M,K) rm; W: (N,K) rm; C: (M,N) rm.
// Tiles: BM=128, BN=64, BK=16. 256 threads = 8 warps in 4(m) x 2(n) grid,
// each warp owns a 32x32 complex tile = (2 m16) x (4 n8) acc frags, R and I.
// tf32 conversion done once at SMEM fill. SMEM row pad = 20 words -> the
// fragment gather (8 rows x 4 cols) hits all 32 banks conflict-free.
// ============================================================================
__global__ __launch_bounds__(256, 2) void cgemm_tc_kernel(const float* __restrict__ Ar,
                                                          const float* __restrict__ Ai,
                                                          const float* __restrict__ Wr,
                                                          const float* __restrict__ Wi,
                                                          const float* __restrict__ bm,
                                                          const float* __restrict__ bp,
                                                          float* __restrict__ Cr,
                                                          float* __restrict__ Ci,
                                                          int M, int N, int K) {
    __shared__ uint32 sAr[128][20], sAi[128][20];
    __shared__ uint32 sWr[64][20],  sWi[64][20];

    int m0 = blockIdx.y * 128, n0 = blockIdx.x * 64;
    int tid = threadIdx.x;
    int warp = tid >> 5, lane = tid & 31;
    int wm = warp & 3, wn = warp >> 2;          // warp tile: rows wm*32, cols wn*32
    int g = lane >> 2, t = lane & 3;            // fragment coords

    float accR[2][4][4], accI[2][4][4];
    #pragma unroll
    for (int mi = 0; mi < 2; mi++)
        #pragma unroll
        for (int ni = 0; ni < 4; ni++)
            #pragma unroll
            for (int e = 0; e < 4; e++) { accR[mi][ni][e] = 0.f; accI[mi][ni][e] = 0.f; }

    for (int k0 = 0; k0 < K; k0 += 16) {
        // fill A tiles: 128x16 floats = 512 float4 per array; 2 per thread
        #pragma unroll
        for (int l = 0; l < 2; l++) {
            int idx = tid + l * 256;
            int r = idx >> 2, c4 = (idx & 3) * 4;
            float4 va = *(const float4*)&Ar[(size_t)(m0 + r) * K + k0 + c4];
            float4 vb = *(const float4*)&Ai[(size_t)(m0 + r) * K + k0 + c4];
            sAr[r][c4]     = to_tf32(va.x); sAr[r][c4 + 1] = to_tf32(va.y);
            sAr[r][c4 + 2] = to_tf32(va.z); sAr[r][c4 + 3] = to_tf32(va.w);
            sAi[r][c4]     = to_tf32(vb.x); sAi[r][c4 + 1] = to_tf32(vb.y);
            sAi[r][c4 + 2] = to_tf32(vb.z); sAi[r][c4 + 3] = to_tf32(vb.w);
        }
        // fill W tiles: 64x16 floats = 256 float4 per array; 1 per thread
        {
            int r = tid >> 2, c4 = (tid & 3) * 4;
            float4 va = *(const float4*)&Wr[(size_t)(n0 + r) * K + k0 + c4];
            float4 vb = *(const float4*)&Wi[(size_t)(n0 + r) * K + k0 + c4];
            sWr[r][c4]     = to_tf32(va.x); sWr[r][c4 + 1] = to_tf32(va.y);
            sWr[r][c4 + 2] = to_tf32(va.z); sWr[r][c4 + 3] = to_tf32(va.w);
            sWi[r][c4]     = to_tf32(vb.x); sWi[r][c4 + 1] = to_tf32(vb.y);
            sWi[r][c4 + 2] = to_tf32(vb.z); sWi[r][c4 + 3] = to_tf32(vb.w);
        }
        __syncthreads();

        #pragma unroll
        for (int kk = 0; kk < 16; kk += 8) {
            // A fragments (rows wm*32 + mi*16 + {g, g+8}, cols kk + {t, t+4})
            uint32 fa[2][4], fb[2][4], fbn[2][4];
            #pragma unroll
            for (int mi = 0; mi < 2; mi++) {
                int r = wm * 32 + mi * 16 + g;
                fa[mi][0] = sAr[r][kk + t];      fa[mi][1] = sAr[r + 8][kk + t];
                fa[mi][2] = sAr[r][kk + t + 4];  fa[mi][3] = sAr[r + 8][kk + t + 4];
                fb[mi][0] = sAi[r][kk + t];      fb[mi][1] = sAi[r + 8][kk + t];
                fb[mi][2] = sAi[r][kk + t + 4];  fb[mi][3] = sAi[r + 8][kk + t + 4];
                #pragma unroll
                for (int e = 0; e < 4; e++) fbn[mi][e] = fb[mi][e] ^ 0x80000000u;
            }
            // B fragments (n rows wn*32 + ni*8 + g, cols kk + {t, t+4})
            uint32 fwr[4][2], fwi[4][2];
            #pragma unroll
            for (int ni = 0; ni < 4; ni++) {
                int n = wn * 32 + ni * 8 + g;
                fwr[ni][0] = sWr[n][kk + t]; fwr[ni][1] = sWr[n][kk + t + 4];
                fwi[ni][0] = sWi[n][kk + t]; fwi[ni][1] = sWi[n][kk + t + 4];
            }
            #pragma unroll
            for (int mi = 0; mi < 2; mi++)
                #pragma unroll
                for (int ni = 0; ni < 4; ni++) {
                    MMA_TF32(accR[mi][ni], fa[mi],  fwr[ni]);
                    MMA_TF32(accR[mi][ni], fbn[mi], fwi[ni]);
                    MMA_TF32(accI[mi][ni], fa[mi],  fwi[ni]);
                    MMA_TF32(accI[mi][ni], fb[mi],  fwr[ni]);
                }
        }
        __syncthreads();
    }

    // epilogue: acc frag element (e0,e1)=row g, cols 2t,2t+1 ; (e2,e3)=row g+8
    #pragma unroll
    for (int ni = 0; ni < 4; ni++) {
        int n = n0 + wn * 32 + ni * 8 + 2 * t;
        float br0 = 0.f, br1 = 0.f, bi0 = 0.f, bi1 = 0.f;
        if (bm) {
            br0 = bm[n] * cosf(bp[n]);     bi0 = bm[n] * sinf(bp[n]);
            br1 = bm[n + 1] * cosf(bp[n + 1]); bi1 = bm[n + 1] * sinf(bp[n + 1]);
        }
        #pragma unroll
        for (int mi = 0; mi < 2; mi++) {
            int r = m0 + wm * 32 + mi * 16 + g;
            float* c0 = accR[mi][ni];
            float* c1 = accI[mi][ni];
            *(float2*)&Cr[(size_t)r * N + n]        = make_float2(c0[0] + br0, c0[1] + br1);
            *(float2*)&Cr[(size_t)(r + 8) * N + n]  = make_float2(c0[2] + br0, c0[3] + br1);
            *(float2*)&Ci[(size_t)r * N + n]        = make_float2(c1[0] + bi0, c1[1] + bi1);
            *(float2*)&Ci[(size_t)(r + 8) * N + n]  = make_float2(c1[2] + bi0, c1[3] + bi1);
        }
    }
}

// RoPE in place on q,k (real & imag). Angles up to 1023 rad -> double sincos.
__global__ __launch_bounds__(256) void rope_kernel(float* __restrict__ qr, float* __restrict__ qi,
                                                   float* __restrict__ kr, float* __restrict__ ki) {
    int idx = blockIdx.x * 256 + threadIdx.x;   // < B*H*S*32 = 1048576
    int j = idx & 31;
    int s = (idx >> 5) & 1023;
    int h = (idx >> 15) & 7;
    int b = idx >> 18;
    double invf = pow(10000.0, -(double)(2 * j) / 64.0);
    double ang = (double)s * invf;
    double sd, cd;
    sincos(ang, &sd, &cd);
    float sn = (float)sd, cs = (float)cd;
    size_t base = (((size_t)b * SS + s) * DM) + h * HDD + j;
    float x0, x1;
    x0 = qr[base]; x1 = qr[base + 32]; qr[base] = x0 * cs - x1 * sn; qr[base + 32] = x1 * cs + x0 * sn;
    x0 = qi[base]; x1 = qi[base + 32]; qi[base] = x0 * cs - x1 * sn; qi[base + 32] = x1 * cs + x0 * sn;
    x0 = kr[base]; x1 = kr[base + 32]; kr[base] = x0 * cs - x1 * sn; kr[base + 32] = x1 * cs + x0 * sn;
    x0 = ki[base]; x1 = ki[base + 32]; ki[base] = x0 * cs - x1 * sn; ki[base + 32] = x1 * cs + x0 * sn;
}

// scores[bh, m, n] = (qr.kr + qi.ki)*scale ; only tiles with nt<=mt (causal)
__global__ __launch_bounds__(256) void scores_kernel(const float* __restrict__ qr,
                                                     const float* __restrict__ qi,
                                                     const float* __restrict__ kr,
                                                     const float* __restrict__ ki,
                                                     float* __restrict__ sc) {
    int bh = blockIdx.x, mt = blockIdx.y, nt = blockIdx.z;
    if (nt > mt) return;
    int b = bh >> 3, h = bh & 7;
    __shared__ float sQr[16][64], sQi[16][64], sKr[16][64], sKi[16][64];
    int m0 = mt * 64, n0 = nt * 64;
    int tx = threadIdx.x, ty = threadIdx.y;
    int tid = ty * 16 + tx;
    const size_t head_off = (size_t)b * SS * DM + (size_t)h * HDD;
    float acc[4][4] = {{0}};
    for (int k0 = 0; k0 < HDD; k0 += 16) {
        #pragma unroll
        for (int l = 0; l < 4; l++) {
            int idx = tid + l * 256;
            int r = idx >> 4, c = idx & 15;
            sQr[c][r] = qr[head_off + (size_t)(m0 + r) * DM + k0 + c];
            sQi[c][r] = qi[head_off + (size_t)(m0 + r) * DM + k0 + c];
            sKr[c][r] = kr[head_off + (size_t)(n0 + r) * DM + k0 + c];
            sKi[c][r] = ki[head_off + (size_t)(n0 + r) * DM + k0 + c];
        }
        __syncthreads();
        #pragma unroll
        for (int kk = 0; kk < 16; kk++) {
            float a[4], b2[4], c2[4], d2[4];
            #pragma unroll
            for (int j = 0; j < 4; j++) {
                a[j] = sQr[kk][ty * 4 + j];
                b2[j] = sQi[kk][ty * 4 + j];
                c2[j] = sKr[kk][tx * 4 + j];
                d2[j] = sKi[kk][tx * 4 + j];
            }
            #pragma unroll
            for (int i2 = 0; i2 < 4; i2++)
                #pragma unroll
                for (int j2 = 0; j2 < 4; j2++) {
                    acc[i2][j2] += a[i2] * c2[j2];
                    acc[i2][j2] += b2[i2] * d2[j2];
                }
        }
        __syncthreads();
    }
    const float scale = 0.125f;  // 1/sqrt(64)
    #pragma unroll
    for (int i2 = 0; i2 < 4; i2++) {
        size_t row = ((size_t)bh * SS + m0 + ty * 4 + i2) * SS;
        #pragma unroll
        for (int j2 = 0; j2 < 4; j2++)
            sc[row + n0 + tx * 4 + j2] = acc[i2][j2] * scale;
    }
}

// causal softmax per row; writes probs for col<=q, zeros for col>q
__global__ __launch_bounds__(256) void softmax_kernel(float* __restrict__ sc) {
    int row = blockIdx.x;          // bh*1024 + q
    int q = row & 1023;
    float* p = sc + (size_t)row * SS;
    int n = q + 1;
    int t = threadIdx.x;
    __shared__ float red[256];

    float mx = -1e30f;
    for (int i = t; i < n; i += 256) mx = fmaxf(mx, p[i]);
    red[t] = mx; __syncthreads();
    for (int s2 = 128; s2 > 0; s2 >>= 1) { if (t < s2) red[t] = fmaxf(red[t], red[t + s2]); __syncthreads(); }
    mx = red[0]; __syncthreads();

    float sum = 0.f;
    for (int i = t; i < n; i += 256) { float e = __expf(p[i] - mx); p[i] = e; sum += e; }
    red[t] = sum; __syncthreads();
    for (int s2 = 128; s2 > 0; s2 >>= 1) { if (t < s2) red[t] += red[t + s2]; __syncthreads(); }
    float inv = 1.0f / red[0];

    for (int i = t; i < n; i += 256) p[i] *= inv;
    for (int i = n + t; i < SS; i += 256) p[i] = 0.f;
}

// out[b, m, h*64+n] = sum_k attn[bh,m,k] * v[b,k,h*64+n]  (r and i), FFMA2
__global__ __launch_bounds__(256) void av_kernel(const float* __restrict__ attn,
                                                 const float* __restrict__ vr,
                                                 const float* __restrict__ vi,
                                                 float* __restrict__ ar_out,
                                                 float* __restrict__ ai_out) {
    int bh = blockIdx.x, mt = blockIdx.y;
    int b = bh >> 3, h = bh & 7;
    __shared__ float sP[16][64], sVr[16][64], sVi[16][64];
    int m0 = mt * 64;
    int tx = threadIdx.x, ty = threadIdx.y;
    int tid = ty * 16 + tx;
    ull accR[4][2], accI[4][2];
    #pragma unroll
    for (int i = 0; i < 4; i++) { accR[i][0] = accR[i][1] = 0ULL; accI[i][0] = accI[i][1] = 0ULL; }
    const size_t vbase = (size_t)b * SS * DM + (size_t)h * HDD;
    int kmax = m0 + 64;  // causal: tail zeros anyway
    for (int k0 = 0; k0 < kmax; k0 += 16) {
        #pragma unroll
        for (int l = 0; l < 4; l++) {
            int idx = tid + l * 256;
            int r = idx >> 4, c = idx & 15;
            sP[c][r] = attn[((size_t)bh * SS + m0 + r) * SS + k0 + c];
            int kk = idx >> 6, nn = idx & 63;
            sVr[kk][nn] = vr[vbase + (size_t)(k0 + kk) * DM + nn];
            sVi[kk][nn] = vi[vbase + (size_t)(k0 + kk) * DM + nn];
        }
        __syncthreads();
        #pragma unroll
        for (int kk = 0; kk < 16; kk++) {
            float4 pv = *(const float4*)&sP[kk][ty * 4];
            ulonglong2 vr2 = *(const ulonglong2*)&sVr[kk][tx * 4];
            ulonglong2 vi2 = *(const ulonglong2*)&sVi[kk][tx * 4];
            float ps[4] = {pv.x, pv.y, pv.z, pv.w};
            ull vrp[2] = {vr2.x, vr2.y};
            ull vip[2] = {vi2.x, vi2.y};
            #pragma unroll
            for (int i = 0; i < 4; i++) {
                ull pP = pk2(ps[i]);
                #pragma unroll
                for (int p = 0; p < 2; p++) {
                    fma2(accR[i][p], pP, vrp[p]);
                    fma2(accI[i][p], pP, vip[p]);
                }
            }
        }
        __syncthreads();
    }
    #pragma unroll
    for (int i = 0; i < 4; i++) {
        size_t orow = (size_t)b * SS * DM + (size_t)(m0 + ty * 4 + i) * DM + h * HDD + tx * 4;
        float2 r0 = up2(accR[i][0]), r1 = up2(accR[i][1]);
        float2 q0 = up2(accI[i][0]), q1 = up2(accI[i][1]);
        *(float4*)&ar_out[orow] = make_float4(r0.x, r0.y, r1.x, r1.y);
        *(float4*)&ai_out[orow] = make_float4(q0.x, q0.y, q1.x, q1.y);
    }
}

__global__ __launch_bounds__(256) void resid_kernel(const float* __restrict__ xr,
                                                    const float* __restrict__ xi,
                                                    const float* __restrict__ ar,
                                                    const float* __restrict__ ai,
                                                    float* __restrict__ out) {
    size_t i = (size_t)blockIdx.x * 256 + threadIdx.x;
    out[i] = xr[i] + ar[i];
    out[NDE + i] = xi[i] + ai[i];
}

__global__ __launch_bounds__(256) void gateact_kernel(float* __restrict__ gr, float* __restrict__ gi,
                                                      const float* __restrict__ ur,
                                                      const float* __restrict__ ui) {
    size_t i = (size_t)blockIdx.x * 256 + threadIdx.x;
    float a = gr[i], b = gi[i];
    float mag = sqrtf(a * a + b * b);
    float s = 1.0f / (1.0f + expf(-mag));
    float gar = a * s, gai = b * s;
    float u = ur[i], v = ui[i];
    gr[i] = gar * u - gai * v;
    gi[i] = gar * v + gai * u;
}

__global__ __launch_bounds__(256) void addout_kernel(const float* __restrict__ dr,
                                                     const float* __restrict__ di,
                                                     float* __restrict__ out) {
    size_t i = (size_t)blockIdx.x * 256 + threadIdx.x;
    out[i] += dr[i];
    out[NDE + i] += di[i];
}

// ---------------------------------------------------------------------------
extern "C" void kernel_launch(void* const* d_in, const int* in_sizes, int n_in,
                              void* d_out, int out_size) {
    const float* x_real = (const float*)d_in[0];
    const float* x_imag = (const float*)d_in[1];
    const float* ln1_gr = (const float*)d_in[2];
    const float* ln1_gi = (const float*)d_in[3];
    const float* ln1_br = (const float*)d_in[4];
    const float* ln1_bi = (const float*)d_in[5];
    const float* q_lm = (const float*)d_in[6];
    const float* q_ph = (const float*)d_in[7];
    const float* q_bm = (const float*)d_in[8];
    const float* q_bp = (const float*)d_in[9];
    const float* k_lm = (const float*)d_in[10];
    const float* k_ph = (const float*)d_in[11];
    const float* k_bm = (const float*)d_in[12];
    const float* k_bp = (const float*)d_in[13];
    const float* v_lm = (const float*)d_in[14];
    const float* v_ph = (const float*)d_in[15];
    const float* v_bm = (const float*)d_in[16];
    const float* v_bp = (const float*)d_in[17];
    const float* o_lm = (const float*)d_in[18];
    const float* o_ph = (const float*)d_in[19];
    const float* o_bm = (const float*)d_in[20];
    const float* o_bp = (const float*)d_in[21];
    const float* ln2_gr = (const float*)d_in[22];
    const float* ln2_gi = (const float*)d_in[23];
    const float* ln2_br = (const float*)d_in[24];
    const float* ln2_bi = (const float*)d_in[25];
    const float* gate_lm = (const float*)d_in[26];
    const float* gate_ph = (const float*)d_in[27];
    const float* up_lm = (const float*)d_in[28];
    const float* up_ph = (const float*)d_in[29];
    const float* down_lm = (const float*)d_in[30];
    const float* down_ph = (const float*)d_in[31];
    float* out = (float*)d_out;

    float* Sp = nullptr;
    cudaGetSymbolAddress((void**)&Sp, g_scratch);

    // scratch layout
    float* qwr = Sp;            float* qwi = qwr + DDE;
    float* kwr = qwi + DDE;     float* kwi = kwr + DDE;
    float* vwr = kwi + DDE;     float* vwi = vwr + DDE;
    float* owr = vwi + DDE;     float* owi = owr + DDE;
    float* gwr = owi + DDE;     float* gwi = gwr + GDE;
    float* uwr = gwi + GDE;     float* uwi = uwr + GDE;
    float* dwr = uwi + GDE;     float* dwi = dwr + GDE;
    float* hr = dwi + GDE;      float* hi = hr + NDE;
    float* qr = hi + NDE;       float* qi = qr + NDE;
    float* kr = qi + NDE;       float* ki = kr + NDE;
    float* vr = ki + NDE;       float* vi = vr + NDE;
    float* ar = vi + NDE;       float* ai = ar + NDE;
    float* gr = ai + NDE;       float* gi = gr + NHE;
    float* ur = gi + NHE;       float* ui = ur + NHE;
    float* sc = ui + NHE;

    dim3 blk2(16, 16);

    // 1) materialize weights W = exp(lm) * e^{i ph}
    make_w_kernel<<<(int)(DDE / 256), 256>>>(q_lm, q_ph, qwr, qwi, (int)DDE);
    make_w_kernel<<<(int)(DDE / 256), 256>>>(k_lm, k_ph, kwr, kwi, (int)DDE);
    make_w_kernel<<<(int)(DDE / 256), 256>>>(v_lm, v_ph, vwr, vwi, (int)DDE);
    make_w_kernel<<<(int)(DDE / 256), 256>>>(o_lm, o_ph, owr, owi, (int)DDE);
    make_w_kernel<<<(int)(GDE / 256), 256>>>(gate_lm, gate_ph, gwr, gwi, (int)GDE);
    make_w_kernel<<<(int)(GDE / 256), 256>>>(up_lm, up_ph, uwr, uwi, (int)GDE);
    make_w_kernel<<<(int)(GDE / 256), 256>>>(down_lm, down_ph, dwr, dwi, (int)GDE);

    // 2) LN1
    cln_kernel<<<NT, 256>>>(x_real, x_imag, ln1_gr, ln1_gi, ln1_br, ln1_bi, hr, hi);

    // 3) QKV projections (tensor cores, tf32)
    cgemm_tc_kernel<<<dim3(DM / 64, NT / 128), 256>>>(hr, hi, qwr, qwi, q_bm, q_bp, qr, qi, NT, DM, DM);
    cgemm_tc_kernel<<<dim3(DM / 64, NT / 128), 256>>>(hr, hi, kwr, kwi, k_bm, k_bp, kr, ki, NT, DM, DM);
    cgemm_tc_kernel<<<dim3(DM / 64, NT / 128), 256>>>(hr, hi, vwr, vwi, v_bm, v_bp, vr, vi, NT, DM, DM);

    // 4) RoPE on q,k
    rope_kernel<<<(BB * HH * SS * (HDD / 2)) / 256, 256>>>(qr, qi, kr, ki);

    // 5) attention (exact fp32 FFMA2)
    scores_kernel<<<dim3(BB * HH, SS / 64, SS / 64), blk2>>>(qr, qi, kr, ki, sc);
    softmax_kernel<<<BB * HH * SS, 256>>>(sc);
    av_kernel<<<dim3(BB * HH, SS / 64), blk2>>>(sc, vr, vi, ar, ai);

    // 6) output projection (reuse qr/qi as o-proj output)
    cgemm_tc_kernel<<<dim3(DM / 64, NT / 128), 256>>>(ar, ai, owr, owi, o_bm, o_bp, qr, qi, NT, DM, DM);

    // 7) residual -> d_out (res_r at [0..N), res_i at [N..2N))
    resid_kernel<<<(int)(NDE / 256), 256>>>(x_real, x_imag, qr, qi, out);

    // 8) LN2 (reads residual from d_out)
    cln_kernel<<<NT, 256>>>(out, out + NDE, ln2_gr, ln2_gi, ln2_br, ln2_bi, hr, hi);

    // 9) FFN (tensor cores, tf32)
    cgemm_tc_kernel<<<dim3(HIDD / 64, NT / 128), 256>>>(hr, hi, gwr, gwi, nullptr, nullptr, gr, gi, NT, HIDD, DM);
    cgemm_tc_kernel<<<dim3(HIDD / 64, NT / 128), 256>>>(hr, hi, uwr, uwi, nullptr, nullptr, ur, ui, NT, HIDD, DM);
    gateact_kernel<<<(int)(NHE / 256), 256>>>(gr, gi, ur, ui);
    // down proj (reuse kr/ki as output)
    cgemm_tc_kernel<<<dim3(DM / 64, NT / 128), 256>>>(gr, gi, dwr, dwi, nullptr, nullptr, kr, ki, NT, DM, HIDD);

    // 10) final residual add into d_out
    addout_kernel<<<(int)(NDE / 256), 256>>>(kr, ki, out);
}